// round 3
// baseline (speedup 1.0000x reference)
#include <cuda_runtime.h>
#include <cstdint>
#include <cstddef>

// Problem dims
#define BATCH   128
#define NLAYERS 12
#define DFEAT   4096
#define DACT    768

// Tiling
#define CTA_N   128
#define NT      6                   // 768 / 128
#define KB      16
#define NKIT    (DFEAT / KB)        // 256
#define NCHUNK  78                  // sum_{i=0..11} (i+1)
#define NCTA    (NCHUNK * NT)       // 468

// smem layout (floats). A: [128][KB] stride 20 (conflict-free frag reads),
// B: [KB][128] stride 136 (8-bank shift -> conflict-free frag reads)
#define ASTR    20
#define BSTR    136
#define AS      (BATCH * ASTR)      // 2560 floats
#define BS      (KB * BSTR)         // 2176 floats
#define STAGE   (AS + BS)           // 4736 floats
#define NSTAGE  3
#define SMEM_FLOATS (NSTAGE * STAGE)     // 14208
#define SMEM_BYTES  (SMEM_FLOATS * 4)    // 56832

// Split-chunk scratch: 78 x 128 x 768 fp32 = 30.7 MB
__device__ float g_scratch[(size_t)NCHUNK * BATCH * DACT];

struct WPtrs { const float* w[NLAYERS]; };

__device__ __forceinline__ uint32_t f2tf32(float f) {
    uint32_t r;
    asm("cvt.rna.tf32.f32 %0, %1;" : "=r"(r) : "f"(f));
    return r;
}

__device__ __forceinline__ void cvt4(float4 v, uint32_t* o) {
    o[0] = f2tf32(v.x); o[1] = f2tf32(v.y); o[2] = f2tf32(v.z); o[3] = f2tf32(v.w);
}

__device__ __forceinline__ void mma_tf32(float* c, const uint32_t* a, const uint32_t* b) {
    asm volatile(
        "mma.sync.aligned.m16n8k8.row.col.f32.tf32.tf32.f32 "
        "{%0,%1,%2,%3}, {%4,%5,%6,%7}, {%8,%9}, {%0,%1,%2,%3};"
        : "+f"(c[0]), "+f"(c[1]), "+f"(c[2]), "+f"(c[3])
        : "r"(a[0]), "r"(a[1]), "r"(a[2]), "r"(a[3]), "r"(b[0]), "r"(b[1]));
}

// ---------------- main GEMM: one CTA per (chunk c=(i,l), n-tile tn) ----------------
// M=128 (batch), N=128, K=4096. tf32 mma.sync, warp tile 64x64 (4 warps 2x2).
__global__ void __launch_bounds__(128, 2)
tri_gemm_kernel(const float* __restrict__ x, WPtrs wp)
{
    extern __shared__ float smem[];
    const int tid = threadIdx.x;
    const int lane = tid & 31;
    const int wid = tid >> 5;
    const int warp_m = wid & 1;         // 0/1 -> m offset 0/64
    const int warp_n = wid >> 1;        // 0/1 -> n offset 0/64

    const int c = blockIdx.x / NT;
    const int tn = blockIdx.x % NT;
    int i = 0;
    while (c >= (i + 1) * (i + 2) / 2) i++;
    const int l = c - i * (i + 1) / 2;

    // W_i[l] : [DFEAT, DACT], take n-columns [tn*128, tn*128+128)
    const float* __restrict__ Wb = wp.w[i] + (size_t)l * DFEAT * DACT + (size_t)tn * CTA_N;
    // x[:, l, :]
    const float* __restrict__ xl = x + (size_t)l * DFEAT;

    // Accumulators: warp 64x64 -> 4 m-tiles x 8 n-tiles x 4 regs
    float acc[4][8][4];
#pragma unroll
    for (int mt = 0; mt < 4; mt++)
#pragma unroll
        for (int nt = 0; nt < 8; nt++)
#pragma unroll
            for (int q = 0; q < 4; q++) acc[mt][nt][q] = 0.f;

    // gmem load descriptors
    // A: thread t, pass p: row m = t/4 + p*32, k4 = (t%4)*4   (coalesced 4-lane groups)
    const int a_m0 = tid >> 2;
    const int a_k4 = (tid & 3) << 2;
    // B: thread t, pass j: k = t%16, n = (t/16)*16 + j*4       (coalesced per 64B chunk)
    const int b_k  = tid & 15;
    const int b_n0 = (tid >> 4) << 4;

    float4 aR[4], bR[4];

    // prologue: load+store stage 0, load stage 1 into regs
    {
        const int kg = 0;
#pragma unroll
        for (int p = 0; p < 4; p++)
            aR[p] = *(const float4*)(xl + (size_t)(a_m0 + p * 32) * (NLAYERS * DFEAT) + kg + a_k4);
#pragma unroll
        for (int j = 0; j < 4; j++)
            bR[j] = *(const float4*)(Wb + (size_t)(kg + b_k) * DACT + b_n0 + j * 4);
        float* Ab = smem;               // stage 0
        float* Bb = smem + AS;
#pragma unroll
        for (int p = 0; p < 4; p++) {
            uint32_t o[4]; cvt4(aR[p], o);
            *(uint4*)(Ab + (a_m0 + p * 32) * ASTR + a_k4) = *(uint4*)o;
        }
#pragma unroll
        for (int j = 0; j < 4; j++) {
            uint32_t o[4]; cvt4(bR[j], o);
            *(uint4*)(Bb + b_k * BSTR + b_n0 + j * 4) = *(uint4*)o;
        }
        const int kg1 = KB;
#pragma unroll
        for (int p = 0; p < 4; p++)
            aR[p] = *(const float4*)(xl + (size_t)(a_m0 + p * 32) * (NLAYERS * DFEAT) + kg1 + a_k4);
#pragma unroll
        for (int j = 0; j < 4; j++)
            bR[j] = *(const float4*)(Wb + (size_t)(kg1 + b_k) * DACT + b_n0 + j * 4);
    }

#pragma unroll 1
    for (int s = 0; s < NKIT; s++) {
        // STS stage s+1 (from regs), LDG stage s+2 (into regs)
        if (s + 1 < NKIT) {
            float* Ab = smem + ((s + 1) % NSTAGE) * STAGE;
            float* Bb = Ab + AS;
#pragma unroll
            for (int p = 0; p < 4; p++) {
                uint32_t o[4]; cvt4(aR[p], o);
                *(uint4*)(Ab + (a_m0 + p * 32) * ASTR + a_k4) = *(uint4*)o;
            }
#pragma unroll
            for (int j = 0; j < 4; j++) {
                uint32_t o[4]; cvt4(bR[j], o);
                *(uint4*)(Bb + b_k * BSTR + b_n0 + j * 4) = *(uint4*)o;
            }
        }
        if (s + 2 < NKIT) {
            const int kg = (s + 2) * KB;
#pragma unroll
            for (int p = 0; p < 4; p++)
                aR[p] = *(const float4*)(xl + (size_t)(a_m0 + p * 32) * (NLAYERS * DFEAT) + kg + a_k4);
#pragma unroll
            for (int j = 0; j < 4; j++)
                bR[j] = *(const float4*)(Wb + (size_t)(kg + b_k) * DACT + b_n0 + j * 4);
        }
        __syncthreads();

        // compute stage s
        const float* Ab = smem + (s % NSTAGE) * STAGE;
        const float* Bb = Ab + AS;
#pragma unroll
        for (int kk = 0; kk < 2; kk++) {
            uint32_t af[4][4];
            uint32_t bf[8][2];
            const int k0 = kk * 8 + (lane & 3);
            const int rA = warp_m * 64 + (lane >> 2);
            const int nB = warp_n * 64 + (lane >> 2);
#pragma unroll
            for (int mt = 0; mt < 4; mt++) {
                const float* ap = Ab + (rA + mt * 16) * ASTR + k0;
                af[mt][0] = __float_as_uint(ap[0]);
                af[mt][1] = __float_as_uint(ap[8 * ASTR]);
                af[mt][2] = __float_as_uint(ap[4]);
                af[mt][3] = __float_as_uint(ap[8 * ASTR + 4]);
            }
#pragma unroll
            for (int nt = 0; nt < 8; nt++) {
                const float* bp = Bb + k0 * BSTR + nB + nt * 8;
                bf[nt][0] = __float_as_uint(bp[0]);
                bf[nt][1] = __float_as_uint(bp[4 * BSTR]);
            }
#pragma unroll
            for (int mt = 0; mt < 4; mt++)
#pragma unroll
                for (int nt = 0; nt < 8; nt++)
                    mma_tf32(acc[mt][nt], af[mt], bf[nt]);
        }
    }

    // Epilogue: write 64x64 warp tile to scratch (fp32), fully deterministic.
    {
        float* dstc = g_scratch + (size_t)c * (BATCH * DACT);
        const int r0 = warp_m * 64 + (lane >> 2);
        const int c0 = tn * CTA_N + warp_n * 64 + (lane & 3) * 2;
#pragma unroll
        for (int mt = 0; mt < 4; mt++) {
#pragma unroll
            for (int nt = 0; nt < 8; nt++) {
                float* d0 = dstc + (size_t)(r0 + mt * 16) * DACT + c0 + nt * 8;
                *(float2*)d0 = make_float2(acc[mt][nt][0], acc[mt][nt][1]);
                float* d1 = d0 + 8 * DACT;
                *(float2*)d1 = make_float2(acc[mt][nt][2], acc[mt][nt][3]);
            }
        }
    }
}

// ---------------- prefix reduce: out[b,i,a] = sum_{l<=i} scratch[(i,l)][b][a] ----------------
__global__ void reduce_kernel(float* __restrict__ out)
{
    int idx = blockIdx.x * blockDim.x + threadIdx.x;
    if (idx >= BATCH * NLAYERS * DACT) return;
    int a = idx % DACT;
    int r = idx / DACT;
    int i = r % NLAYERS;
    int b = r / NLAYERS;
    int base = i * (i + 1) / 2;
    float s = 0.f;
#pragma unroll 1
    for (int l = 0; l <= i; l++)
        s += g_scratch[(size_t)(base + l) * (BATCH * DACT) + (size_t)b * DACT + a];
    out[idx] = s;
}

// ---------------- launch ----------------
extern "C" void kernel_launch(void* const* d_in, const int* in_sizes, int n_in,
                              void* d_out, int out_size)
{
    const float* x = (const float*)d_in[0];
    WPtrs wp;
    for (int j = 0; j < NLAYERS; j++) wp.w[j] = (const float*)d_in[1 + j];

    cudaFuncSetAttribute(tri_gemm_kernel, cudaFuncAttributeMaxDynamicSharedMemorySize, SMEM_BYTES);
    tri_gemm_kernel<<<NCTA, 128, SMEM_BYTES>>>(x, wp);

    int total = BATCH * NLAYERS * DACT;
    reduce_kernel<<<(total + 255) / 256, 256>>>((float*)d_out);
}

// round 6
// speedup vs baseline: 1.5502x; 1.5502x over previous
#include <cuda_runtime.h>
#include <cstdint>
#include <cstddef>

// Problem dims
#define BATCH   128
#define NLAYERS 12
#define DFEAT   4096
#define DACT    768

// Tiling
#define CTA_N   128
#define NT      6                   // 768 / 128
#define KB      16
#define NCHUNK  78                  // sum_{i=0..11} (i+1)
#define NTASK   (NCHUNK * NT)       // 468 (c, tn) tasks
#define NFULL   296                 // tasks 0..295: full K (one occ-2 wave)
#define NSPLIT  (NTASK - NFULL)     // 172 tasks split into 4 quarter-K CTAs
#define NCTA    (NFULL + NSPLIT * 4)  // 984

// smem layout (floats). A: [128][20], B: [16][136] (conflict-free frag reads)
#define ASTR    20
#define BSTR    136
#define AS      (BATCH * ASTR)      // 2560 floats
#define BS      (KB * BSTR)         // 2176 floats
#define STAGE   (AS + BS)           // 4736 floats
#define NSTAGE  3
#define SMEM_BYTES  (NSTAGE * STAGE * 4)   // 56832

// One 128x128 fp32 tile per CTA slot: 984 * 64KB = 64.5 MB
#define TILE_ELEMS 16384
__device__ float g_scratch[(size_t)NCTA * TILE_ELEMS];

struct WPtrs { const float* w[NLAYERS]; };

__device__ __forceinline__ uint32_t f2tf32(float f) {
    uint32_t r;
    asm("cvt.rna.tf32.f32 %0, %1;" : "=r"(r) : "f"(f));
    return r;
}

__device__ __forceinline__ void cvt4(float4 v, uint32_t* o) {
    o[0] = f2tf32(v.x); o[1] = f2tf32(v.y); o[2] = f2tf32(v.z); o[3] = f2tf32(v.w);
}

__device__ __forceinline__ void mma_tf32(float* c, const uint32_t* a, const uint32_t* b) {
    asm volatile(
        "mma.sync.aligned.m16n8k8.row.col.f32.tf32.tf32.f32 "
        "{%0,%1,%2,%3}, {%4,%5,%6,%7}, {%8,%9}, {%0,%1,%2,%3};"
        : "+f"(c[0]), "+f"(c[1]), "+f"(c[2]), "+f"(c[3])
        : "r"(a[0]), "r"(a[1]), "r"(a[2]), "r"(a[3]), "r"(b[0]), "r"(b[1]));
}

// ---------------- main GEMM ----------------
// Task t=(c,tn): out-tile [128 batch x 128 act-cols] of chunk c. Full tasks do
// K=4096; split tasks run as 4 CTAs of K=1024 each writing separate slots.
// 256 threads, 8 warps (2x4), warp tile 64x32, tf32 mma m16n8k8.
__global__ void __launch_bounds__(256, 2)
tri_gemm_kernel(const float* __restrict__ x, WPtrs wp)
{
    extern __shared__ float smem[];
    const int tid  = threadIdx.x;
    const int lane = tid & 31;
    const int wid  = tid >> 5;
    const int warp_m = wid & 1;       // 0/1 -> m offset 0/64
    const int warp_n = wid >> 1;      // 0..3 -> n offset 0/32/64/96

    const int bid = blockIdx.x;
    int t, kstart, nkit;
    if (bid < NFULL) { t = bid; kstart = 0; nkit = DFEAT / KB; }
    else {
        t = NFULL + ((bid - NFULL) >> 2);
        kstart = ((bid - NFULL) & 3) << 10;     // q * 1024
        nkit = 1024 / KB;                        // 64
    }
    const int c  = t / NT;
    const int tn = t % NT;
    int i = 0;
    while (c >= (i + 1) * (i + 2) / 2) i++;
    const int l = c - i * (i + 1) / 2;

    const float* __restrict__ Wb = wp.w[i] + (size_t)l * DFEAT * DACT + (size_t)tn * CTA_N;
    const float* __restrict__ xl = x + (size_t)l * DFEAT;

    float acc[4][4][4];
#pragma unroll
    for (int mt = 0; mt < 4; mt++)
#pragma unroll
        for (int nt = 0; nt < 4; nt++)
#pragma unroll
            for (int q = 0; q < 4; q++) acc[mt][nt][q] = 0.f;

    // Loader mapping (256 threads, 2 passes each for A and B)
    const int a_row = tid >> 2;           // + j*64
    const int a_k4  = (tid & 3) << 2;
    const int b_k   = tid >> 5;           // + j*8
    const int b_n4  = (tid & 31) << 2;

    const float* pA0 = xl + (size_t)a_row * (NLAYERS * DFEAT) + kstart + a_k4;
    const float* pA1 = pA0 + (size_t)64 * (NLAYERS * DFEAT);
    const float* pB0 = Wb + (size_t)(kstart + b_k) * DACT + b_n4;
    const float* pB1 = pB0 + (size_t)8 * DACT;

    float4 aR0, aR1, bR0, bR1;

    // prologue: LDG stage0 -> STS stage0 -> LDG stage1 (held in regs)
    aR0 = *(const float4*)pA0; aR1 = *(const float4*)pA1;
    bR0 = *(const float4*)pB0; bR1 = *(const float4*)pB1;
    pA0 += KB; pA1 += KB; pB0 += (size_t)KB * DACT; pB1 += (size_t)KB * DACT;
    {
        float* Ab = smem; float* Bb = smem + AS;
        uint32_t o[4];
        cvt4(aR0, o); *(uint4*)(Ab + a_row * ASTR + a_k4) = *(uint4*)o;
        cvt4(aR1, o); *(uint4*)(Ab + (a_row + 64) * ASTR + a_k4) = *(uint4*)o;
        cvt4(bR0, o); *(uint4*)(Bb + b_k * BSTR + b_n4) = *(uint4*)o;
        cvt4(bR1, o); *(uint4*)(Bb + (b_k + 8) * BSTR + b_n4) = *(uint4*)o;
    }
    aR0 = *(const float4*)pA0; aR1 = *(const float4*)pA1;
    bR0 = *(const float4*)pB0; bR1 = *(const float4*)pB1;
    pA0 += KB; pA1 += KB; pB0 += (size_t)KB * DACT; pB1 += (size_t)KB * DACT;

    int buf_sts = 1, buf_cmp = 0;
#pragma unroll 1
    for (int s = 0; s < nkit; s++) {
        if (s + 1 < nkit) {
            float* Ab = smem + buf_sts * STAGE;
            float* Bb = Ab + AS;
            uint32_t o[4];
            cvt4(aR0, o); *(uint4*)(Ab + a_row * ASTR + a_k4) = *(uint4*)o;
            cvt4(aR1, o); *(uint4*)(Ab + (a_row + 64) * ASTR + a_k4) = *(uint4*)o;
            cvt4(bR0, o); *(uint4*)(Bb + b_k * BSTR + b_n4) = *(uint4*)o;
            cvt4(bR1, o); *(uint4*)(Bb + (b_k + 8) * BSTR + b_n4) = *(uint4*)o;
            buf_sts++; if (buf_sts == NSTAGE) buf_sts = 0;
        }
        if (s + 2 < nkit) {
            aR0 = *(const float4*)pA0; aR1 = *(const float4*)pA1;
            bR0 = *(const float4*)pB0; bR1 = *(const float4*)pB1;
            pA0 += KB; pA1 += KB; pB0 += (size_t)KB * DACT; pB1 += (size_t)KB * DACT;
        }
        __syncthreads();

        const float* Ab = smem + buf_cmp * STAGE;
        const float* Bb = Ab + AS;
        buf_cmp++; if (buf_cmp == NSTAGE) buf_cmp = 0;
#pragma unroll
        for (int kk = 0; kk < 2; kk++) {
            const int k0 = kk * 8 + (lane & 3);
            const float* ap = Ab + (warp_m * 64 + (lane >> 2)) * ASTR + k0;
            const float* bp = Bb + k0 * BSTR + warp_n * 32 + (lane >> 2);
            uint32_t af[4][4], bf[4][2];
#pragma unroll
            for (int mt = 0; mt < 4; mt++) {
                const float* aq = ap + mt * 16 * ASTR;
                af[mt][0] = __float_as_uint(aq[0]);
                af[mt][1] = __float_as_uint(aq[8 * ASTR]);
                af[mt][2] = __float_as_uint(aq[4]);
                af[mt][3] = __float_as_uint(aq[8 * ASTR + 4]);
            }
#pragma unroll
            for (int nt = 0; nt < 4; nt++) {
                const float* bq = bp + nt * 8;
                bf[nt][0] = __float_as_uint(bq[0]);
                bf[nt][1] = __float_as_uint(bq[4 * BSTR]);
            }
#pragma unroll
            for (int mt = 0; mt < 4; mt++)
#pragma unroll
                for (int nt = 0; nt < 4; nt++)
                    mma_tf32(acc[mt][nt], af[mt], bf[nt]);
        }
    }

    // Epilogue: write this CTA's 128x128 tile to its private slot (deterministic)
    {
        float* dstc = g_scratch + (size_t)bid * TILE_ELEMS;
        const int r0 = warp_m * 64 + (lane >> 2);
        const int c0 = warp_n * 32 + (lane & 3) * 2;
#pragma unroll
        for (int mt = 0; mt < 4; mt++) {
#pragma unroll
            for (int nt = 0; nt < 4; nt++) {
                float* d0 = dstc + (size_t)(r0 + mt * 16) * CTA_N + c0 + nt * 8;
                *(float2*)d0 = make_float2(acc[mt][nt][0], acc[mt][nt][1]);
                float* d1 = d0 + 8 * CTA_N;
                *(float2*)d1 = make_float2(acc[mt][nt][2], acc[mt][nt][3]);
            }
        }
    }
}

// ---------------- reduce: out[b,i,a] = sum over l<=i of task (i,l)'s slot(s) ----------------
__global__ void reduce_kernel(float* __restrict__ out)
{
    int idx = blockIdx.x * blockDim.x + threadIdx.x;
    if (idx >= BATCH * NLAYERS * DACT) return;
    const int a = idx % DACT;
    const int r = idx / DACT;
    const int i = r % NLAYERS;
    const int b = r / NLAYERS;
    const int tn = a >> 7;
    const int ai = a & 127;
    const int c0 = i * (i + 1) / 2;
    const size_t eoff = (size_t)b * CTA_N + ai;

    float s = 0.f;
#pragma unroll
    for (int l = 0; l < NLAYERS; l++) {
        if (l <= i) {
            const int t = (c0 + l) * NT + tn;
            if (t < NFULL) {
                s += g_scratch[(size_t)t * TILE_ELEMS + eoff];
            } else {
                const float* p = g_scratch +
                    ((size_t)NFULL + (size_t)(t - NFULL) * 4) * TILE_ELEMS + eoff;
                s += p[0] + p[TILE_ELEMS] + p[2 * TILE_ELEMS] + p[3 * TILE_ELEMS];
            }
        }
    }
    out[idx] = s;
}

// ---------------- launch ----------------
extern "C" void kernel_launch(void* const* d_in, const int* in_sizes, int n_in,
                              void* d_out, int out_size)
{
    const float* x = (const float*)d_in[0];
    WPtrs wp;
    for (int j = 0; j < NLAYERS; j++) wp.w[j] = (const float*)d_in[1 + j];

    cudaFuncSetAttribute(tri_gemm_kernel, cudaFuncAttributeMaxDynamicSharedMemorySize, SMEM_BYTES);
    tri_gemm_kernel<<<NCTA, 256, SMEM_BYTES>>>(x, wp);

    int total = BATCH * NLAYERS * DACT;
    reduce_kernel<<<(total + 255) / 256, 256>>>((float*)d_out);
}

// round 8
// speedup vs baseline: 1.8880x; 1.2179x over previous
#include <cuda_runtime.h>
#include <cuda_fp16.h>
#include <cstdint>
#include <cstddef>

// Problem dims
#define BATCH   128
#define NLAYERS 12
#define DFEAT   4096
#define DACT    768

// Tiling
#define CTA_N   128
#define NT      6                   // 768 / 128
#define KB      16
#define NCHUNK  78                  // sum_{i=0..11} (i+1)
#define NTASK   (NCHUNK * NT)       // 468 (c, tn) tasks
#define NFULL   296                 // tasks 0..295: full K (one occ-2 wave)
#define NSPLIT  (NTASK - NFULL)     // 172 tasks split into 4 quarter-K CTAs
#define NCTA    (NFULL + NSPLIT * 4)  // 984

// smem (halves). A: [128][ASTR], B: [16][BSTR]. Strides chosen so the 8 row
// pointers of every ldmatrix land in distinct 4-bank windows.
#define ASTR    24                  // halves (48B rows: 12-bank stride)
#define BSTR    136                 // halves (272B rows: 4-bank stride)
#define AS_H    (BATCH * ASTR)      // 3072 halves
#define BS_H    (KB * BSTR)         // 2176 halves
#define STAGE_H (AS_H + BS_H)       // 5248 halves = 10496 B
#define NSTAGE  3
#define SMEM_BYTES (NSTAGE * STAGE_H * 2)   // 31488

// One 128x128 fp32 tile per CTA slot: 984 * 64KB = 64.5 MB
#define TILE_ELEMS 16384
__device__ float g_scratch[(size_t)NCTA * TILE_ELEMS];

struct WPtrs { const float* w[NLAYERS]; };

__device__ __forceinline__ uint32_t smem_u32(const void* p) {
    uint32_t a;
    asm("{ .reg .u64 t; cvta.to.shared.u64 t, %1; cvt.u32.u64 %0, t; }" : "=r"(a) : "l"(p));
    return a;
}

__device__ __forceinline__ uint2 pack4(float4 v) {
    half2 h0 = __floats2half2_rn(v.x, v.y);   // .x in low half
    half2 h1 = __floats2half2_rn(v.z, v.w);
    uint2 r;
    r.x = *(uint32_t*)&h0;
    r.y = *(uint32_t*)&h1;
    return r;
}

__device__ __forceinline__ void ldmx4(uint32_t* r, uint32_t addr) {
    asm volatile("ldmatrix.sync.aligned.m8n8.x4.shared.b16 {%0,%1,%2,%3}, [%4];"
                 : "=r"(r[0]), "=r"(r[1]), "=r"(r[2]), "=r"(r[3]) : "r"(addr));
}
__device__ __forceinline__ void ldmx4t(uint32_t* r, uint32_t addr) {
    asm volatile("ldmatrix.sync.aligned.m8n8.x4.trans.shared.b16 {%0,%1,%2,%3}, [%4];"
                 : "=r"(r[0]), "=r"(r[1]), "=r"(r[2]), "=r"(r[3]) : "r"(addr));
}

__device__ __forceinline__ void mma_fp16(float* c, const uint32_t* a, const uint32_t* b) {
    asm volatile(
        "mma.sync.aligned.m16n8k16.row.col.f32.f16.f16.f32 "
        "{%0,%1,%2,%3}, {%4,%5,%6,%7}, {%8,%9}, {%0,%1,%2,%3};"
        : "+f"(c[0]), "+f"(c[1]), "+f"(c[2]), "+f"(c[3])
        : "r"(a[0]), "r"(a[1]), "r"(a[2]), "r"(a[3]), "r"(b[0]), "r"(b[1]));
}

// ---------------- main GEMM ----------------
// Task t=(c,tn): out-tile [128 batch x 128 act-cols] of chunk c. Full tasks do
// K=4096; split tasks run as 4 CTAs of K=1024 each writing separate slots.
// 256 threads, 8 warps (2x4), warp tile 64x32, fp16 mma m16n8k16, fp32 accum.
__global__ void __launch_bounds__(256, 2)
tri_gemm_kernel(const float* __restrict__ x, WPtrs wp)
{
    extern __shared__ half smemh[];
    const uint32_t sb = smem_u32(smemh);
    const int tid  = threadIdx.x;
    const int lane = tid & 31;
    const int wid  = tid >> 5;
    const int warp_m = wid & 1;       // 0/1 -> m offset 0/64
    const int warp_n = wid >> 1;      // 0..3 -> n offset 0/32/64/96

    const int bid = blockIdx.x;
    int t, kstart, nkit;
    if (bid < NFULL) { t = bid; kstart = 0; nkit = DFEAT / KB; }
    else {
        t = NFULL + ((bid - NFULL) >> 2);
        kstart = ((bid - NFULL) & 3) << 10;     // q * 1024
        nkit = 1024 / KB;                        // 64
    }
    const int c  = t / NT;
    const int tn = t % NT;
    int i = 0;
    while (c >= (i + 1) * (i + 2) / 2) i++;
    const int l = c - i * (i + 1) / 2;

    const float* __restrict__ Wb = wp.w[i] + (size_t)l * DFEAT * DACT + (size_t)tn * CTA_N;
    const float* __restrict__ xl = x + (size_t)l * DFEAT;

    float acc[4][4][4];
#pragma unroll
    for (int mt = 0; mt < 4; mt++)
#pragma unroll
        for (int nt = 0; nt < 4; nt++)
#pragma unroll
            for (int q = 0; q < 4; q++) acc[mt][nt][q] = 0.f;

    // Loader mapping (256 threads, 2 passes each for A and B)
    const int a_row = tid >> 2;           // + pass*64
    const int a_k4  = (tid & 3) << 2;
    const int b_k   = tid >> 5;           // + pass*8
    const int b_n4  = (tid & 31) << 2;

    const float* pA0 = xl + (size_t)a_row * (NLAYERS * DFEAT) + kstart + a_k4;
    const float* pA1 = pA0 + (size_t)64 * (NLAYERS * DFEAT);
    const float* pB0 = Wb + (size_t)(kstart + b_k) * DACT + b_n4;
    const float* pB1 = pB0 + (size_t)8 * DACT;

    // smem half-index bases for this thread's stores
    const uint32_t sA0 = (uint32_t)(a_row * ASTR + a_k4);
    const uint32_t sA1 = (uint32_t)((a_row + 64) * ASTR + a_k4);
    const uint32_t sB0 = (uint32_t)(AS_H + b_k * BSTR + b_n4);
    const uint32_t sB1 = (uint32_t)(AS_H + (b_k + 8) * BSTR + b_n4);

    // Per-thread ldmatrix address components (byte offsets within a stage)
    // A: row = warp_m*64 + mt*16 + (lane&7) + ((lane>>3)&1)*8 ; kcol = (lane>>4)*8
    const uint32_t a_lm_row = (uint32_t)(warp_m * 64 + (lane & 7) + ((lane >> 3) & 1) * 8);
    const uint32_t a_lm_off = (a_lm_row * ASTR + ((lane >> 4) << 3)) * 2;
    // B: k = (lane&7) + ((lane>>3)&1)*8 ; ncol = warp_n*32 + nt2*16 + (lane>>4)*8
    const uint32_t b_lm_k   = (uint32_t)((lane & 7) + ((lane >> 3) & 1) * 8);
    const uint32_t b_lm_off = (uint32_t)(AS_H * 2) +
                              (b_lm_k * BSTR + warp_n * 32 + ((lane >> 4) << 3)) * 2;

    float4 aR0, aR1, bR0, bR1;

    // prologue: LDG stage0 -> STS stage0 -> LDG stage1 (held in regs)
    aR0 = *(const float4*)pA0; aR1 = *(const float4*)pA1;
    bR0 = *(const float4*)pB0; bR1 = *(const float4*)pB1;
    pA0 += KB; pA1 += KB; pB0 += (size_t)KB * DACT; pB1 += (size_t)KB * DACT;
    {
        *(uint2*)(smemh + sA0) = pack4(aR0);
        *(uint2*)(smemh + sA1) = pack4(aR1);
        *(uint2*)(smemh + sB0) = pack4(bR0);
        *(uint2*)(smemh + sB1) = pack4(bR1);
    }
    aR0 = *(const float4*)pA0; aR1 = *(const float4*)pA1;
    bR0 = *(const float4*)pB0; bR1 = *(const float4*)pB1;
    pA0 += KB; pA1 += KB; pB0 += (size_t)KB * DACT; pB1 += (size_t)KB * DACT;

    int buf_sts = 1, buf_cmp = 0;
#pragma unroll 1
    for (int s = 0; s < nkit; s++) {
        if (s + 1 < nkit) {
            half* st = smemh + buf_sts * STAGE_H;
            *(uint2*)(st + sA0) = pack4(aR0);
            *(uint2*)(st + sA1) = pack4(aR1);
            *(uint2*)(st + sB0) = pack4(bR0);
            *(uint2*)(st + sB1) = pack4(bR1);
            buf_sts++; if (buf_sts == NSTAGE) buf_sts = 0;
        }
        if (s + 2 < nkit) {
            aR0 = *(const float4*)pA0; aR1 = *(const float4*)pA1;
            bR0 = *(const float4*)pB0; bR1 = *(const float4*)pB1;
            pA0 += KB; pA1 += KB; pB0 += (size_t)KB * DACT; pB1 += (size_t)KB * DACT;
        }
        __syncthreads();

        const uint32_t stage_b = sb + (uint32_t)(buf_cmp * STAGE_H * 2);
        buf_cmp++; if (buf_cmp == NSTAGE) buf_cmp = 0;

        // Fragments via ldmatrix (one k16 step per stage)
        uint32_t af[4][4];
#pragma unroll
        for (int mt = 0; mt < 4; mt++)
            ldmx4(af[mt], stage_b + a_lm_off + (uint32_t)(mt * 16 * ASTR * 2));
        uint32_t bf[4][2];
        {
            uint32_t r[4];
            ldmx4t(r, stage_b + b_lm_off);
            bf[0][0] = r[0]; bf[0][1] = r[1]; bf[1][0] = r[2]; bf[1][1] = r[3];
            ldmx4t(r, stage_b + b_lm_off + 16 * 2);
            bf[2][0] = r[0]; bf[2][1] = r[1]; bf[3][0] = r[2]; bf[3][1] = r[3];
        }
#pragma unroll
        for (int mt = 0; mt < 4; mt++)
#pragma unroll
            for (int nt = 0; nt < 4; nt++)
                mma_fp16(acc[mt][nt], af[mt], bf[nt]);
    }

    // Epilogue: write this CTA's 128x128 tile to its private slot (deterministic)
    {
        float* dstc = g_scratch + (size_t)bid * TILE_ELEMS;
        const int r0 = warp_m * 64 + (lane >> 2);
        const int c0 = warp_n * 32 + (lane & 3) * 2;
#pragma unroll
        for (int mt = 0; mt < 4; mt++) {
#pragma unroll
            for (int nt = 0; nt < 4; nt++) {
                float* d0 = dstc + (size_t)(r0 + mt * 16) * CTA_N + c0 + nt * 8;
                *(float2*)d0 = make_float2(acc[mt][nt][0], acc[mt][nt][1]);
                float* d1 = d0 + 8 * CTA_N;
                *(float2*)d1 = make_float2(acc[mt][nt][2], acc[mt][nt][3]);
            }
        }
    }
}

// ---------------- reduce: out[b,i,a] = sum over l<=i of task (i,l)'s slot(s) ----------------
// float4-vectorized: one thread per 4 output elements.
__global__ void reduce_kernel(float* __restrict__ out)
{
    const int nvec = BATCH * NLAYERS * DACT / 4;
    int idx = blockIdx.x * blockDim.x + threadIdx.x;
    if (idx >= nvec) return;
    const int a4 = (idx % (DACT / 4)) << 2;
    const int r  = idx / (DACT / 4);
    const int i  = r % NLAYERS;
    const int b  = r / NLAYERS;
    const int tn = a4 >> 7;
    const int ai = a4 & 127;
    const int c0 = i * (i + 1) / 2;
    const size_t eoff = (size_t)b * CTA_N + ai;

    float4 s = make_float4(0.f, 0.f, 0.f, 0.f);
#pragma unroll
    for (int l = 0; l < NLAYERS; l++) {
        if (l <= i) {
            const int t = (c0 + l) * NT + tn;
            if (t < NFULL) {
                float4 v = *(const float4*)(g_scratch + (size_t)t * TILE_ELEMS + eoff);
                s.x += v.x; s.y += v.y; s.z += v.z; s.w += v.w;
            } else {
                const float* p = g_scratch +
                    ((size_t)NFULL + (size_t)(t - NFULL) * 4) * TILE_ELEMS + eoff;
                float4 v0 = *(const float4*)(p);
                float4 v1 = *(const float4*)(p + TILE_ELEMS);
                float4 v2 = *(const float4*)(p + 2 * TILE_ELEMS);
                float4 v3 = *(const float4*)(p + 3 * TILE_ELEMS);
                s.x += v0.x + v1.x + v2.x + v3.x;
                s.y += v0.y + v1.y + v2.y + v3.y;
                s.z += v0.z + v1.z + v2.z + v3.z;
                s.w += v0.w + v1.w + v2.w + v3.w;
            }
        }
    }
    *(float4*)(out + (size_t)idx * 4) = s;
}

// ---------------- launch ----------------
extern "C" void kernel_launch(void* const* d_in, const int* in_sizes, int n_in,
                              void* d_out, int out_size)
{
    const float* x = (const float*)d_in[0];
    WPtrs wp;
    for (int j = 0; j < NLAYERS; j++) wp.w[j] = (const float*)d_in[1 + j];

    cudaFuncSetAttribute(tri_gemm_kernel, cudaFuncAttributeMaxDynamicSharedMemorySize, SMEM_BYTES);
    tri_gemm_kernel<<<NCTA, 256, SMEM_BYTES>>>(x, wp);

    int nvec = BATCH * NLAYERS * DACT / 4;
    reduce_kernel<<<(nvec + 255) / 256, 256>>>((float*)d_out);
}

// round 13
// speedup vs baseline: 2.6060x; 1.3803x over previous
#include <cuda_runtime.h>
#include <cuda_fp16.h>
#include <cstdint>
#include <cstddef>

// Problem dims
#define BATCH   128
#define NLAYERS 12
#define DFEAT   4096
#define DACT    768

// Tiling
#define CTA_N   128
#define NT      6                   // 768 / 128
#define KB      32
#define NCHUNK  78                  // sum_{i=0..11} (i+1)
#define NTASK   (NCHUNK * NT)       // 468 (c, tn) tasks
#define NFULL   296                 // tasks 0..295: full K (one occ-2 wave)
#define NSPLIT  (NTASK - NFULL)     // 172 tasks split into 4 quarter-K CTAs
#define NCTA    (NFULL + NSPLIT * 4)  // 984

// smem (halves). A: [128][ASTR], B: [32][BSTR].
// ASTR=40 halves (80B rows, 20-bank stride): ldmatrix rows hit 8 distinct banks.
// BSTR=136 halves (272B rows, 4-bank stride): ldmatrix rows distinct.
#define ASTR    40
#define BSTR    136
#define AS_H    (BATCH * ASTR)      // 5120 halves
#define BS_H    (KB * BSTR)         // 4352 halves
#define STAGE_H (AS_H + BS_H)       // 9472 halves = 18944 B
#define NSTAGE  3
#define SMEM_BYTES (NSTAGE * STAGE_H * 2)   // 56832

// One 128x128 fp32 tile per CTA slot: 984 * 64KB = 64.5 MB
#define TILE_ELEMS 16384
__device__ float g_scratch[(size_t)NCTA * TILE_ELEMS];
// x pre-converted to fp16, layout [l][b][k] (contiguous per l-slice): 12.6 MB
__device__ half g_x16[(size_t)NLAYERS * BATCH * DFEAT];

struct WPtrs { const float* w[NLAYERS]; };

__device__ __forceinline__ uint32_t smem_u32(const void* p) {
    uint32_t a;
    asm("{ .reg .u64 t; cvta.to.shared.u64 t, %1; cvt.u32.u64 %0, t; }" : "=r"(a) : "l"(p));
    return a;
}

__device__ __forceinline__ uint2 pack4(float4 v) {
    half2 h0 = __floats2half2_rn(v.x, v.y);   // .x in low half
    half2 h1 = __floats2half2_rn(v.z, v.w);
    uint2 r;
    r.x = *(uint32_t*)&h0;
    r.y = *(uint32_t*)&h1;
    return r;
}

__device__ __forceinline__ void ldmx4(uint32_t* r, uint32_t addr) {
    asm volatile("ldmatrix.sync.aligned.m8n8.x4.shared.b16 {%0,%1,%2,%3}, [%4];"
                 : "=r"(r[0]), "=r"(r[1]), "=r"(r[2]), "=r"(r[3]) : "r"(addr));
}
__device__ __forceinline__ void ldmx4t(uint32_t* r, uint32_t addr) {
    asm volatile("ldmatrix.sync.aligned.m8n8.x4.trans.shared.b16 {%0,%1,%2,%3}, [%4];"
                 : "=r"(r[0]), "=r"(r[1]), "=r"(r[2]), "=r"(r[3]) : "r"(addr));
}

__device__ __forceinline__ void mma_fp16(float* c, const uint32_t* a, const uint32_t* b) {
    asm volatile(
        "mma.sync.aligned.m16n8k16.row.col.f32.f16.f16.f32 "
        "{%0,%1,%2,%3}, {%4,%5,%6,%7}, {%8,%9}, {%0,%1,%2,%3};"
        : "+f"(c[0]), "+f"(c[1]), "+f"(c[2]), "+f"(c[3])
        : "r"(a[0]), "r"(a[1]), "r"(a[2]), "r"(a[3]), "r"(b[0]), "r"(b[1]));
}

// ---------------- x -> fp16 preconvert, [b][l][k] -> [l][b][k] ----------------
__global__ void xcvt_kernel(const float* __restrict__ x)
{
    int idx = blockIdx.x * blockDim.x + threadIdx.x;          // one per 8 elements
    const int nv = NLAYERS * BATCH * DFEAT / 8;
    if (idx >= nv) return;
    const int k8 = (idx % (DFEAT / 8)) * 8;
    const int r  = idx / (DFEAT / 8);
    const int b  = r % BATCH;
    const int l  = r / BATCH;
    const float* src = x + ((size_t)b * NLAYERS + l) * DFEAT + k8;
    float4 v0 = *(const float4*)src;
    float4 v1 = *(const float4*)(src + 4);
    uint2 p0 = pack4(v0), p1 = pack4(v1);
    uint4 o = make_uint4(p0.x, p0.y, p1.x, p1.y);
    *(uint4*)(g_x16 + ((size_t)l * BATCH + b) * DFEAT + k8) = o;
}

// ---------------- main GEMM ----------------
// Task t=(c,tn): out-tile [128 batch x 128 act-cols] of chunk c. Full tasks do
// K=4096; split tasks run as 4 CTAs of K=1024 each writing separate slots.
// 256 threads, 8 warps (2x4), warp tile 64x32, fp16 mma m16n8k16, fp32 accum.
// KB=32: two k16 steps per stage, halving barrier count vs KB=16.
__global__ void __launch_bounds__(256, 2)
tri_gemm_kernel(WPtrs wp)
{
    extern __shared__ half smemh[];
    const uint32_t sb = smem_u32(smemh);
    const int tid  = threadIdx.x;
    const int lane = tid & 31;
    const int wid  = tid >> 5;
    const int warp_m = wid & 1;       // 0/1 -> m offset 0/64
    const int warp_n = wid >> 1;      // 0..3 -> n offset 0/32/64/96

    const int bid = blockIdx.x;
    int t, kstart, nkit;
    if (bid < NFULL) { t = bid; kstart = 0; nkit = DFEAT / KB; }        // 128
    else {
        t = NFULL + ((bid - NFULL) >> 2);
        kstart = ((bid - NFULL) & 3) << 10;     // q * 1024
        nkit = 1024 / KB;                        // 32
    }
    const int c  = t / NT;
    const int tn = t % NT;
    int i = 0;
    while (c >= (i + 1) * (i + 2) / 2) i++;
    const int l = c - i * (i + 1) / 2;

    const float* __restrict__ Wb = wp.w[i] + (size_t)l * DFEAT * DACT + (size_t)tn * CTA_N;
    const half*  __restrict__ xl = g_x16 + (size_t)l * BATCH * DFEAT;

    float acc[4][4][4];
#pragma unroll
    for (int mt = 0; mt < 4; mt++)
#pragma unroll
        for (int nt = 0; nt < 4; nt++)
#pragma unroll
            for (int q = 0; q < 4; q++) acc[mt][nt][q] = 0.f;

    // Loader mapping (256 threads)
    // A (fp16 gmem): rows a_row, a_row+64; 8 halves at col a_c8
    const int a_row = tid >> 2;
    const int a_c8  = (tid & 3) << 3;
    // B (fp32 gmem): row b_k, 4 floats at col b_c + 32j, j=0..3
    const int b_k = tid >> 3;
    const int b_c = (tid & 7) << 2;

    const half*  pA0 = xl + (size_t)a_row * DFEAT + kstart + a_c8;
    const half*  pA1 = pA0 + (size_t)64 * DFEAT;
    const float* pB  = Wb + (size_t)(kstart + b_k) * DACT + b_c;

    // smem half-index store bases
    const uint32_t sA0 = (uint32_t)(a_row * ASTR + a_c8);
    const uint32_t sA1 = (uint32_t)((a_row + 64) * ASTR + a_c8);
    const uint32_t sB  = (uint32_t)(AS_H + b_k * BSTR + b_c);

    // ldmatrix address components (byte offsets within a stage)
    const uint32_t a_lm_row = (uint32_t)(warp_m * 64 + (lane & 7) + ((lane >> 3) & 1) * 8);
    const uint32_t a_lm_c   = (uint32_t)((lane >> 4) << 3);
    const uint32_t a_lm_off = (a_lm_row * ASTR + a_lm_c) * 2;
    const uint32_t b_lm_k   = (uint32_t)((lane & 7) + ((lane >> 3) & 1) * 8);
    const uint32_t b_lm_off = (uint32_t)(AS_H * 2) +
                              (b_lm_k * BSTR + warp_n * 32 + ((lane >> 4) << 3)) * 2;

    uint4 aR0, aR1;
    float4 bR[4];

    // prologue: LDG stage0 -> STS stage0 -> LDG stage1 (held in regs)
    aR0 = *(const uint4*)pA0; aR1 = *(const uint4*)pA1;
#pragma unroll
    for (int j = 0; j < 4; j++) bR[j] = *(const float4*)(pB + 32 * j);
    pA0 += KB; pA1 += KB; pB += (size_t)KB * DACT;
    {
        *(uint4*)(smemh + sA0) = aR0;
        *(uint4*)(smemh + sA1) = aR1;
#pragma unroll
        for (int j = 0; j < 4; j++) *(uint2*)(smemh + sB + 32 * j) = pack4(bR[j]);
    }
    aR0 = *(const uint4*)pA0; aR1 = *(const uint4*)pA1;
#pragma unroll
    for (int j = 0; j < 4; j++) bR[j] = *(const float4*)(pB + 32 * j);
    pA0 += KB; pA1 += KB; pB += (size_t)KB * DACT;

    int buf_sts = 1, buf_cmp = 0;
#pragma unroll 1
    for (int s = 0; s < nkit; s++) {
        if (s + 1 < nkit) {
            half* st = smemh + buf_sts * STAGE_H;
            *(uint4*)(st + sA0) = aR0;
            *(uint4*)(st + sA1) = aR1;
#pragma unroll
            for (int j = 0; j < 4; j++) *(uint2*)(st + sB + 32 * j) = pack4(bR[j]);
            buf_sts++; if (buf_sts == NSTAGE) buf_sts = 0;
        }
        if (s + 2 < nkit) {
            aR0 = *(const uint4*)pA0; aR1 = *(const uint4*)pA1;
#pragma unroll
            for (int j = 0; j < 4; j++) bR[j] = *(const float4*)(pB + 32 * j);
            pA0 += KB; pA1 += KB; pB += (size_t)KB * DACT;
        }
        __syncthreads();

        const uint32_t stage_b = sb + (uint32_t)(buf_cmp * STAGE_H * 2);
        buf_cmp++; if (buf_cmp == NSTAGE) buf_cmp = 0;

#pragma unroll
        for (int kk = 0; kk < 2; kk++) {
            uint32_t af[4][4];
#pragma unroll
            for (int mt = 0; mt < 4; mt++)
                ldmx4(af[mt], stage_b + a_lm_off +
                      (uint32_t)((mt * 16 * ASTR + kk * 16) * 2));
            uint32_t bf[4][2];
            {
                uint32_t r[4];
                const uint32_t bo = stage_b + b_lm_off + (uint32_t)(kk * 16 * BSTR * 2);
                ldmx4t(r, bo);
                bf[0][0] = r[0]; bf[0][1] = r[1]; bf[1][0] = r[2]; bf[1][1] = r[3];
                ldmx4t(r, bo + 16 * 2);
                bf[2][0] = r[0]; bf[2][1] = r[1]; bf[3][0] = r[2]; bf[3][1] = r[3];
            }
#pragma unroll
            for (int mt = 0; mt < 4; mt++)
#pragma unroll
                for (int nt = 0; nt < 4; nt++)
                    mma_fp16(acc[mt][nt], af[mt], bf[nt]);
        }
    }

    // Epilogue: write this CTA's 128x128 tile to its private slot (deterministic)
    {
        float* dstc = g_scratch + (size_t)bid * TILE_ELEMS;
        const int r0 = warp_m * 64 + (lane >> 2);
        const int c0 = warp_n * 32 + (lane & 3) * 2;
#pragma unroll
        for (int mt = 0; mt < 4; mt++) {
#pragma unroll
            for (int nt = 0; nt < 4; nt++) {
                float* d0 = dstc + (size_t)(r0 + mt * 16) * CTA_N + c0 + nt * 8;
                *(float2*)d0 = make_float2(acc[mt][nt][0], acc[mt][nt][1]);
                float* d1 = d0 + 8 * CTA_N;
                *(float2*)d1 = make_float2(acc[mt][nt][2], acc[mt][nt][3]);
            }
        }
    }
}

// ---------------- reduce: out[b,i,a] = sum over l<=i of task (i,l)'s slot(s) ----------------
__global__ void reduce_kernel(float* __restrict__ out)
{
    const int nvec = BATCH * NLAYERS * DACT / 4;
    int idx = blockIdx.x * blockDim.x + threadIdx.x;
    if (idx >= nvec) return;
    const int a4 = (idx % (DACT / 4)) << 2;
    const int r  = idx / (DACT / 4);
    const int i  = r % NLAYERS;
    const int b  = r / NLAYERS;
    const int tn = a4 >> 7;
    const int ai = a4 & 127;
    const int c0 = i * (i + 1) / 2;
    const size_t eoff = (size_t)b * CTA_N + ai;

    float4 s = make_float4(0.f, 0.f, 0.f, 0.f);
#pragma unroll
    for (int l = 0; l < NLAYERS; l++) {
        if (l <= i) {
            const int t = (c0 + l) * NT + tn;
            if (t < NFULL) {
                float4 v = *(const float4*)(g_scratch + (size_t)t * TILE_ELEMS + eoff);
                s.x += v.x; s.y += v.y; s.z += v.z; s.w += v.w;
            } else {
                const float* p = g_scratch +
                    ((size_t)NFULL + (size_t)(t - NFULL) * 4) * TILE_ELEMS + eoff;
                float4 v0 = *(const float4*)(p);
                float4 v1 = *(const float4*)(p + TILE_ELEMS);
                float4 v2 = *(const float4*)(p + 2 * TILE_ELEMS);
                float4 v3 = *(const float4*)(p + 3 * TILE_ELEMS);
                s.x += v0.x + v1.x + v2.x + v3.x;
                s.y += v0.y + v1.y + v2.y + v3.y;
                s.z += v0.z + v1.z + v2.z + v3.z;
                s.w += v0.w + v1.w + v2.w + v3.w;
            }
        }
    }
    *(float4*)(out + (size_t)idx * 4) = s;
}

// ---------------- launch ----------------
extern "C" void kernel_launch(void* const* d_in, const int* in_sizes, int n_in,
                              void* d_out, int out_size)
{
    const float* x = (const float*)d_in[0];
    WPtrs wp;
    for (int j = 0; j < NLAYERS; j++) wp.w[j] = (const float*)d_in[1 + j];

    int nx = NLAYERS * BATCH * DFEAT / 8;
    xcvt_kernel<<<(nx + 255) / 256, 256>>>(x);

    cudaFuncSetAttribute(tri_gemm_kernel, cudaFuncAttributeMaxDynamicSharedMemorySize, SMEM_BYTES);
    tri_gemm_kernel<<<NCTA, 256, SMEM_BYTES>>>(wp);

    int nvec = BATCH * NLAYERS * DACT / 4;
    reduce_kernel<<<(nvec + 255) / 256, 256>>>((float*)d_out);
}